// round 1
// baseline (speedup 1.0000x reference)
#include <cuda_runtime.h>
#include <math.h>

#define FIN 256
#define ND  16

// scratch (static device arrays — no allocations)
__device__ float g_Gr[FIN*ND];
__device__ float g_Gi[FIN*ND];
__device__ float g_A [FIN*ND];          // [k][n]
__device__ float g_c [ND];
__device__ float g_kw[9*ND];            // BN-folded depthwise weights [tap][d]
__device__ float g_kb[ND];              // BN-folded bias
__device__ float g_y [2*256*256*ND];    // intermediate y grid (8 MB)

// ---------------------------------------------------------------------------
// pre1: G[k,d] = sum_m e^{-2pi i m k/256} (Wr[m,d] + i Wi[m,d])
// ---------------------------------------------------------------------------
__global__ void __launch_bounds__(256) pre1_kernel(const float* __restrict__ Wr,
                                                   const float* __restrict__ Wi)
{
    __shared__ float ct[256], st[256];
    int tid = threadIdx.x;
    {
        float ang = 6.283185307179586f * (float)tid / 256.0f;
        float s, c; sincosf(ang, &s, &c);
        ct[tid] = c; st[tid] = s;
    }
    __syncthreads();

    int i = blockIdx.x * 256 + tid;      // 0..4095
    int k = i >> 4, d = i & 15;
    float gr = 0.f, gi = 0.f;
    for (int m = 0; m < 256; m++) {
        int t = (m * k) & 255;
        float c = ct[t], s = st[t];
        float wr = Wr[m * 16 + d];
        float wi = Wi[m * 16 + d];
        // e^{-i theta}(wr + i wi) = (c wr + s wi) + i (c wi - s wr)
        gr = fmaf(c, wr, fmaf(s, wi, gr));
        gi = fmaf(c, wi, fmaf(-s, wr, gi));
    }
    g_Gr[i] = gr;
    g_Gi[i] = gi;
}

// ---------------------------------------------------------------------------
// pre2: A[k,n] = (1/16) sum_d [Gr cos(2pi nd/16) - Gi sin(2pi nd/16)]
//       c[n], BN-folded conv weights/bias
// ---------------------------------------------------------------------------
__global__ void __launch_bounds__(256) pre2_kernel(const float* __restrict__ br,
                                                   const float* __restrict__ bi,
                                                   const float* __restrict__ dwk,
                                                   const float* __restrict__ dwb,
                                                   const float* __restrict__ gamma,
                                                   const float* __restrict__ beta,
                                                   const float* __restrict__ mmean,
                                                   const float* __restrict__ mvar)
{
    __shared__ float c16[16], s16[16];
    int tid = threadIdx.x;
    if (tid < 16) {
        float ang = 6.283185307179586f * (float)tid / 16.0f;
        float s, c; sincosf(ang, &s, &c);
        c16[tid] = c; s16[tid] = s;
    }
    __syncthreads();

    int i = blockIdx.x * 256 + tid;      // 0..4095
    int k = i >> 4, n = i & 15;
    float acc = 0.f;
#pragma unroll
    for (int d = 0; d < 16; d++) {
        int u = (n * d) & 15;
        acc = fmaf(g_Gr[k * 16 + d], c16[u], fmaf(-g_Gi[k * 16 + d], s16[u], acc));
    }
    g_A[k * 16 + n] = acc * 0.0625f;

    if (blockIdx.x == 0) {
        if (tid < 16) {
            float cc = 0.f;
#pragma unroll
            for (int d = 0; d < 16; d++) {
                int u = (tid * d) & 15;
                cc += (br[d] - bi[d]) * c16[u] - (br[d] + bi[d]) * s16[u];
            }
            g_c[tid] = cc * 0.0625f;
            float scale = gamma[tid] * rsqrtf(mvar[tid] + 1e-5f);
            g_kb[tid] = (dwb[tid] - mmean[tid]) * scale + beta[tid];
        }
        if (tid < 144) {
            int d = tid & 15;
            float scale = gamma[d] * rsqrtf(mvar[d] + 1e-5f);
            g_kw[tid] = dwk[tid] * scale;
        }
    }
}

// ---------------------------------------------------------------------------
// main GEMM: y[patch, n] = A[n,:] . p + c[n]
// block = 128 threads = one (b, ph) patch row (256 patches)
// thread: cg = t&3 (4 channels), pg = t>>2; owns patches p = j*32+pg, j=0..7
// ---------------------------------------------------------------------------
__global__ void __launch_bounds__(128) fno_gemm_kernel(const float* __restrict__ x)
{
    __shared__ float xs[256 * 20];       // 256 patches, stride 20 words (pad 4)
    __shared__ float As[FIN * ND];       // A transposed-friendly: [k][16]

    int t   = threadIdx.x;
    int bid = blockIdx.x;                // b*256 + ph
    int b   = bid >> 8;
    int ph  = bid & 255;

    {   // stage A into smem (4096 floats)
        const float4* A4  = (const float4*)g_A;
        float4*       As4 = (float4*)As;
#pragma unroll
        for (int it = 0; it < 8; it++)
            As4[t + it * 128] = A4[t + it * 128];
    }

    int cg = t & 3;
    int pg = t >> 2;                     // 0..31
    float4 acc[8];
#pragma unroll
    for (int jj = 0; jj < 8; jj++) acc[jj] = make_float4(0.f, 0.f, 0.f, 0.f);

    const float* xbase = x + (size_t)(b * 4096 + ph * 16) * 4096;

    for (int kr = 0; kr < 16; kr++) {
        __syncthreads();
        // stage one image row (4096 floats), repacked to stride-20 per patch
        const float4* row4 = (const float4*)(xbase + (size_t)kr * 4096);
#pragma unroll
        for (int it = 0; it < 8; it++) {
            int g4 = t + it * 128;       // float4 index 0..1023
            float4 v = row4[g4];
            int g = g4 << 2;
            int p = g >> 4, kc = g & 15;
            *(float4*)&xs[p * 20 + kc] = v;
        }
        __syncthreads();

#pragma unroll
        for (int kc4 = 0; kc4 < 4; kc4++) {
            int k0 = kr * 16 + kc4 * 4;
            const float* Ab = &As[k0 * 16 + cg * 4];
            float4 A0 = *(const float4*)(Ab);
            float4 A1 = *(const float4*)(Ab + 16);
            float4 A2 = *(const float4*)(Ab + 32);
            float4 A3 = *(const float4*)(Ab + 48);
#pragma unroll
            for (int jj = 0; jj < 8; jj++) {
                int p = jj * 32 + pg;
                float4 xv = *(const float4*)&xs[p * 20 + kc4 * 4];
                acc[jj].x = fmaf(xv.x, A0.x, fmaf(xv.y, A1.x, fmaf(xv.z, A2.x, fmaf(xv.w, A3.x, acc[jj].x))));
                acc[jj].y = fmaf(xv.x, A0.y, fmaf(xv.y, A1.y, fmaf(xv.z, A2.y, fmaf(xv.w, A3.y, acc[jj].y))));
                acc[jj].z = fmaf(xv.x, A0.z, fmaf(xv.y, A1.z, fmaf(xv.z, A2.z, fmaf(xv.w, A3.z, acc[jj].z))));
                acc[jj].w = fmaf(xv.x, A0.w, fmaf(xv.y, A1.w, fmaf(xv.z, A2.w, fmaf(xv.w, A3.w, acc[jj].w))));
            }
        }
    }

    float4 cc = ((const float4*)g_c)[cg];
    float4* y4 = (float4*)g_y;
#pragma unroll
    for (int jj = 0; jj < 8; jj++) {
        int p = jj * 32 + pg;
        float4 o = acc[jj];
        o.x += cc.x; o.y += cc.y; o.z += cc.z; o.w += cc.w;
        y4[(bid * 256 + p) * 4 + cg] = o;
    }
}

// ---------------------------------------------------------------------------
// depthwise 3x3 SAME conv (BN folded) evaluated only at resized positions
// out[b,i,j,d] = conv(y)[b, 2i+1, 2j+1, d]
// ---------------------------------------------------------------------------
__global__ void __launch_bounds__(256) conv_resize_kernel(float* __restrict__ out)
{
    int lin = blockIdx.x * 256 + threadIdx.x;   // 0..131071
    int cg = lin & 3;
    int j  = (lin >> 2) & 127;
    int i  = (lin >> 9) & 127;
    int b  = lin >> 16;

    int r1 = 2 * i + 1;
    int c1 = 2 * j + 1;

    const float4* y4  = (const float4*)g_y;
    const float4* kw4 = (const float4*)g_kw;
    float4 kb = ((const float4*)g_kb)[cg];
    float sx = kb.x, sy = kb.y, sz = kb.z, sw = kb.w;

#pragma unroll
    for (int dy = -1; dy <= 1; dy++) {
        int r = r1 + dy;                         // r >= 0 always
        if (r > 255) continue;
#pragma unroll
        for (int dx = -1; dx <= 1; dx++) {
            int c = c1 + dx;                     // c >= 0 always
            if (c > 255) continue;
            float4 v = y4[((b * 256 + r) * 256 + c) * 4 + cg];
            float4 w = kw4[((dy + 1) * 3 + (dx + 1)) * 4 + cg];
            sx = fmaf(v.x, w.x, sx);
            sy = fmaf(v.y, w.y, sy);
            sz = fmaf(v.z, w.z, sz);
            sw = fmaf(v.w, w.w, sw);
        }
    }
    ((float4*)out)[((b * 128 + i) * 128 + j) * 4 + cg] = make_float4(sx, sy, sz, sw);
}

// ---------------------------------------------------------------------------
extern "C" void kernel_launch(void* const* d_in, const int* in_sizes, int n_in,
                              void* d_out, int out_size)
{
    const float* x     = (const float*)d_in[0];
    const float* Wr    = (const float*)d_in[1];
    const float* br    = (const float*)d_in[2];
    const float* Wi    = (const float*)d_in[3];
    const float* bi    = (const float*)d_in[4];
    const float* dwk   = (const float*)d_in[5];
    const float* dwb   = (const float*)d_in[6];
    const float* gamma = (const float*)d_in[7];
    const float* beta  = (const float*)d_in[8];
    const float* mmean = (const float*)d_in[9];
    const float* mvar  = (const float*)d_in[10];

    pre1_kernel<<<16, 256>>>(Wr, Wi);
    pre2_kernel<<<16, 256>>>(br, bi, dwk, dwb, gamma, beta, mmean, mvar);
    fno_gemm_kernel<<<512, 128>>>(x);
    conv_resize_kernel<<<512, 256>>>((float*)d_out);
}

// round 2
// speedup vs baseline: 1.0252x; 1.0252x over previous
#include <cuda_runtime.h>
#include <math.h>

#define FIN 256
#define ND  16

// scratch (static device arrays — no allocations)
__device__ float g_Gr[FIN*ND];
__device__ float g_Gi[FIN*ND];
__device__ float g_A [FIN*ND];          // [k][n]
__device__ float g_c [ND];
__device__ float g_kw[9*ND];            // BN-folded depthwise weights [tap][d]
__device__ float g_kb[ND];              // BN-folded bias
__device__ float g_y [2*256*256*ND];    // intermediate y grid (8 MB)

// ---------------------------------------------------------------------------
// pre1: G[k,d] = sum_m e^{-2pi i m k/256} (Wr[m,d] + i Wi[m,d])
// ---------------------------------------------------------------------------
__global__ void __launch_bounds__(256) pre1_kernel(const float* __restrict__ Wr,
                                                   const float* __restrict__ Wi)
{
    __shared__ float ct[256], st[256];
    int tid = threadIdx.x;
    {
        float ang = 6.283185307179586f * (float)tid / 256.0f;
        float s, c; sincosf(ang, &s, &c);
        ct[tid] = c; st[tid] = s;
    }
    __syncthreads();

    int i = blockIdx.x * 256 + tid;      // 0..4095
    int k = i >> 4, d = i & 15;
    float grA = 0.f, giA = 0.f, grB = 0.f, giB = 0.f;
#pragma unroll 4
    for (int m = 0; m < 256; m += 2) {
        int t0 = (m * k) & 255;
        int t1 = ((m + 1) * k) & 255;
        float c0 = ct[t0], s0 = st[t0];
        float c1 = ct[t1], s1 = st[t1];
        float wr0 = Wr[m * 16 + d],       wi0 = Wi[m * 16 + d];
        float wr1 = Wr[(m + 1) * 16 + d], wi1 = Wi[(m + 1) * 16 + d];
        grA = fmaf(c0, wr0, fmaf(s0, wi0, grA));
        giA = fmaf(c0, wi0, fmaf(-s0, wr0, giA));
        grB = fmaf(c1, wr1, fmaf(s1, wi1, grB));
        giB = fmaf(c1, wi1, fmaf(-s1, wr1, giB));
    }
    g_Gr[i] = grA + grB;
    g_Gi[i] = giA + giB;
}

// ---------------------------------------------------------------------------
// pre2: A[k,n] = (1/16) sum_d [Gr cos(2pi nd/16) - Gi sin(2pi nd/16)]
//       c[n], BN-folded conv weights/bias
// ---------------------------------------------------------------------------
__global__ void __launch_bounds__(256) pre2_kernel(const float* __restrict__ br,
                                                   const float* __restrict__ bi,
                                                   const float* __restrict__ dwk,
                                                   const float* __restrict__ dwb,
                                                   const float* __restrict__ gamma,
                                                   const float* __restrict__ beta,
                                                   const float* __restrict__ mmean,
                                                   const float* __restrict__ mvar)
{
    __shared__ float c16[16], s16[16];
    int tid = threadIdx.x;
    if (tid < 16) {
        float ang = 6.283185307179586f * (float)tid / 16.0f;
        float s, c; sincosf(ang, &s, &c);
        c16[tid] = c; s16[tid] = s;
    }
    __syncthreads();

    int i = blockIdx.x * 256 + tid;      // 0..4095
    int k = i >> 4, n = i & 15;
    float acc = 0.f;
#pragma unroll
    for (int d = 0; d < 16; d++) {
        int u = (n * d) & 15;
        acc = fmaf(g_Gr[k * 16 + d], c16[u], fmaf(-g_Gi[k * 16 + d], s16[u], acc));
    }
    g_A[k * 16 + n] = acc * 0.0625f;

    if (blockIdx.x == 0) {
        if (tid < 16) {
            float cc = 0.f;
#pragma unroll
            for (int d = 0; d < 16; d++) {
                int u = (tid * d) & 15;
                cc += (br[d] - bi[d]) * c16[u] - (br[d] + bi[d]) * s16[u];
            }
            g_c[tid] = cc * 0.0625f;
            float scale = gamma[tid] * rsqrtf(mvar[tid] + 1e-5f);
            g_kb[tid] = (dwb[tid] - mmean[tid]) * scale + beta[tid];
        }
        if (tid < 144) {
            int d = tid & 15;
            float scale = gamma[d] * rsqrtf(mvar[d] + 1e-5f);
            g_kw[tid] = dwk[tid] * scale;
        }
    }
}

// ---------------------------------------------------------------------------
// main GEMM: y[patch, n] = A[n,:] . p + c[n]
// block = 128 threads = one (b, ph) patch row (256 patches)
// thread: cg = t&3 (4 channels), pg = t>>2; owns patches p = j*32+pg, j=0..7
// Register double-buffer: LDG for row kr+1 issued before compute on row kr.
// ---------------------------------------------------------------------------
__global__ void __launch_bounds__(128, 4) fno_gemm_kernel(const float* __restrict__ x)
{
    __shared__ float xs[256 * 20];       // 256 patches, stride 20 words (pad 4)
    __shared__ float As[FIN * ND];       // A: [k][16]

    int t   = threadIdx.x;
    int bid = blockIdx.x;                // b*256 + ph
    int b   = bid >> 8;
    int ph  = bid & 255;

    {   // stage A into smem (4096 floats)
        const float4* A4  = (const float4*)g_A;
        float4*       As4 = (float4*)As;
#pragma unroll
        for (int it = 0; it < 8; it++)
            As4[t + it * 128] = A4[t + it * 128];
    }

    int cg = t & 3;
    int pg = t >> 2;                     // 0..31
    float4 acc[8];
#pragma unroll
    for (int jj = 0; jj < 8; jj++) acc[jj] = make_float4(0.f, 0.f, 0.f, 0.f);

    const float* xbase = x + (size_t)(b * 4096 + ph * 16) * 4096;

    // prefetch row 0 into registers
    float4 v[8];
    {
        const float4* row4 = (const float4*)xbase;
#pragma unroll
        for (int it = 0; it < 8; it++)
            v[it] = row4[t + it * 128];
    }

    for (int kr = 0; kr < 16; kr++) {
        __syncthreads();                 // xs free (prev compute done; also A ready on kr=0)
        // repack registers -> smem, stride-20 per patch
#pragma unroll
        for (int it = 0; it < 8; it++) {
            int g4 = t + it * 128;       // float4 index 0..1023
            int g  = g4 << 2;
            int p = g >> 4, kc = g & 15;
            *(float4*)&xs[p * 20 + kc] = v[it];
        }
        __syncthreads();                 // xs ready
        // prefetch next row — LDG latency hidden behind compute below
        if (kr < 15) {
            const float4* nrow = (const float4*)(xbase + (size_t)(kr + 1) * 4096);
#pragma unroll
            for (int it = 0; it < 8; it++)
                v[it] = nrow[t + it * 128];
        }

#pragma unroll
        for (int kc4 = 0; kc4 < 4; kc4++) {
            int k0 = kr * 16 + kc4 * 4;
            const float* Ab = &As[k0 * 16 + cg * 4];
            float4 A0 = *(const float4*)(Ab);
            float4 A1 = *(const float4*)(Ab + 16);
            float4 A2 = *(const float4*)(Ab + 32);
            float4 A3 = *(const float4*)(Ab + 48);
#pragma unroll
            for (int jj = 0; jj < 8; jj++) {
                int p = jj * 32 + pg;
                float4 xv = *(const float4*)&xs[p * 20 + kc4 * 4];
                acc[jj].x = fmaf(xv.x, A0.x, fmaf(xv.y, A1.x, fmaf(xv.z, A2.x, fmaf(xv.w, A3.x, acc[jj].x))));
                acc[jj].y = fmaf(xv.x, A0.y, fmaf(xv.y, A1.y, fmaf(xv.z, A2.y, fmaf(xv.w, A3.y, acc[jj].y))));
                acc[jj].z = fmaf(xv.x, A0.z, fmaf(xv.y, A1.z, fmaf(xv.z, A2.z, fmaf(xv.w, A3.z, acc[jj].z))));
                acc[jj].w = fmaf(xv.x, A0.w, fmaf(xv.y, A1.w, fmaf(xv.z, A2.w, fmaf(xv.w, A3.w, acc[jj].w))));
            }
        }
    }

    float4 cc = ((const float4*)g_c)[cg];
    float4* y4 = (float4*)g_y;
#pragma unroll
    for (int jj = 0; jj < 8; jj++) {
        int p = jj * 32 + pg;
        float4 o = acc[jj];
        o.x += cc.x; o.y += cc.y; o.z += cc.z; o.w += cc.w;
        y4[(bid * 256 + p) * 4 + cg] = o;
    }
}

// ---------------------------------------------------------------------------
// depthwise 3x3 SAME conv (BN folded) at resized positions.
// Two vertical outputs per thread: i = 2*iq and 2*iq+1 share row 4*iq+2.
// 15 loads serve 2 outputs (vs 18).
// ---------------------------------------------------------------------------
__global__ void __launch_bounds__(256) conv_resize_kernel(float* __restrict__ out)
{
    int lin = blockIdx.x * 256 + threadIdx.x;   // 0..65535
    int cg = lin & 3;
    int j  = (lin >> 2) & 127;
    int iq = (lin >> 9) & 63;
    int b  = lin >> 15;

    int i0 = 2 * iq;
    int c1 = 2 * j + 1;
    int rbase = 4 * iq;                          // = (2*i0+1) - 1

    const float4* y4  = (const float4*)g_y;
    const float4* kw4 = (const float4*)g_kw;
    float4 kb = ((const float4*)g_kb)[cg];
    float4 s0 = kb, s1 = kb;

#pragma unroll
    for (int rr = 0; rr < 5; rr++) {
        int r = rbase + rr;
        if (r > 255) continue;                   // only rr=4 at iq=63
#pragma unroll
        for (int dx = -1; dx <= 1; dx++) {
            int c = c1 + dx;                     // c >= 0 always
            if (c > 255) continue;
            float4 v = y4[((b * 256 + r) * 256 + c) * 4 + cg];
            if (rr < 3) {                        // output i0: taps rows rr=0,1,2
                float4 w = kw4[(rr * 3 + (dx + 1)) * 4 + cg];
                s0.x = fmaf(v.x, w.x, s0.x);
                s0.y = fmaf(v.y, w.y, s0.y);
                s0.z = fmaf(v.z, w.z, s0.z);
                s0.w = fmaf(v.w, w.w, s0.w);
            }
            if (rr >= 2) {                       // output i0+1: taps rows rr=2,3,4
                float4 w = kw4[((rr - 2) * 3 + (dx + 1)) * 4 + cg];
                s1.x = fmaf(v.x, w.x, s1.x);
                s1.y = fmaf(v.y, w.y, s1.y);
                s1.z = fmaf(v.z, w.z, s1.z);
                s1.w = fmaf(v.w, w.w, s1.w);
            }
        }
    }
    float4* o4 = (float4*)out;
    o4[((b * 128 + i0) * 128 + j) * 4 + cg]       = s0;
    o4[((b * 128 + i0 + 1) * 128 + j) * 4 + cg]   = s1;
}

// ---------------------------------------------------------------------------
extern "C" void kernel_launch(void* const* d_in, const int* in_sizes, int n_in,
                              void* d_out, int out_size)
{
    const float* x     = (const float*)d_in[0];
    const float* Wr    = (const float*)d_in[1];
    const float* br    = (const float*)d_in[2];
    const float* Wi    = (const float*)d_in[3];
    const float* bi    = (const float*)d_in[4];
    const float* dwk   = (const float*)d_in[5];
    const float* dwb   = (const float*)d_in[6];
    const float* gamma = (const float*)d_in[7];
    const float* beta  = (const float*)d_in[8];
    const float* mmean = (const float*)d_in[9];
    const float* mvar  = (const float*)d_in[10];

    pre1_kernel<<<16, 256>>>(Wr, Wi);
    pre2_kernel<<<16, 256>>>(br, bi, dwk, dwb, gamma, beta, mmean, mvar);
    fno_gemm_kernel<<<512, 128>>>(x);
    conv_resize_kernel<<<256, 256>>>((float*)d_out);
}

// round 3
// speedup vs baseline: 1.0842x; 1.0575x over previous
#include <cuda_runtime.h>
#include <math.h>
#include <stdint.h>

#define FIN 256
#define ND  16

// scratch (static device arrays — no allocations)
__device__ float g_Gr[FIN*ND];
__device__ float g_Gi[FIN*ND];
__device__ float g_A [FIN*ND];          // [k][n]
__device__ float g_c [ND];
__device__ float g_kw[9*ND];            // BN-folded depthwise weights [tap][d]
__device__ float g_kb[ND];              // BN-folded bias
__device__ float g_y [2*256*256*ND];    // intermediate y grid (8 MB)

__device__ __forceinline__ uint32_t smem_u32(const void* p) {
    uint32_t a;
    asm("{ .reg .u64 t; cvta.to.shared.u64 t, %1; cvt.u32.u64 %0, t; }"
        : "=r"(a) : "l"(p));
    return a;
}
__device__ __forceinline__ void cp_async16(uint32_t dst, const void* src) {
    asm volatile("cp.async.cg.shared.global [%0], [%1], 16;" :: "r"(dst), "l"(src));
}

// ---------------------------------------------------------------------------
// pre1: G[k,d] = sum_m e^{-2pi i m k/256} (Wr[m,d] + i Wi[m,d])
// ---------------------------------------------------------------------------
__global__ void __launch_bounds__(256) pre1_kernel(const float* __restrict__ Wr,
                                                   const float* __restrict__ Wi)
{
    __shared__ float ct[256], st[256];
    int tid = threadIdx.x;
    {
        float ang = 6.283185307179586f * (float)tid / 256.0f;
        float s, c; sincosf(ang, &s, &c);
        ct[tid] = c; st[tid] = s;
    }
    __syncthreads();

    int i = blockIdx.x * 256 + tid;      // 0..4095
    int k = i >> 4, d = i & 15;
    float grA = 0.f, giA = 0.f, grB = 0.f, giB = 0.f;
#pragma unroll 4
    for (int m = 0; m < 256; m += 2) {
        int t0 = (m * k) & 255;
        int t1 = ((m + 1) * k) & 255;
        float c0 = ct[t0], s0 = st[t0];
        float c1 = ct[t1], s1 = st[t1];
        float wr0 = Wr[m * 16 + d],       wi0 = Wi[m * 16 + d];
        float wr1 = Wr[(m + 1) * 16 + d], wi1 = Wi[(m + 1) * 16 + d];
        grA = fmaf(c0, wr0, fmaf(s0, wi0, grA));
        giA = fmaf(c0, wi0, fmaf(-s0, wr0, giA));
        grB = fmaf(c1, wr1, fmaf(s1, wi1, grB));
        giB = fmaf(c1, wi1, fmaf(-s1, wr1, giB));
    }
    g_Gr[i] = grA + grB;
    g_Gi[i] = giA + giB;
}

// ---------------------------------------------------------------------------
// pre2: A[k,n] = (1/16) sum_d [Gr cos(2pi nd/16) - Gi sin(2pi nd/16)]
//       c[n], BN-folded conv weights/bias
// ---------------------------------------------------------------------------
__global__ void __launch_bounds__(256) pre2_kernel(const float* __restrict__ br,
                                                   const float* __restrict__ bi,
                                                   const float* __restrict__ dwk,
                                                   const float* __restrict__ dwb,
                                                   const float* __restrict__ gamma,
                                                   const float* __restrict__ beta,
                                                   const float* __restrict__ mmean,
                                                   const float* __restrict__ mvar)
{
    __shared__ float c16[16], s16[16];
    int tid = threadIdx.x;
    if (tid < 16) {
        float ang = 6.283185307179586f * (float)tid / 16.0f;
        float s, c; sincosf(ang, &s, &c);
        c16[tid] = c; s16[tid] = s;
    }
    __syncthreads();

    int i = blockIdx.x * 256 + tid;      // 0..4095
    int k = i >> 4, n = i & 15;
    float acc = 0.f;
#pragma unroll
    for (int d = 0; d < 16; d++) {
        int u = (n * d) & 15;
        acc = fmaf(g_Gr[k * 16 + d], c16[u], fmaf(-g_Gi[k * 16 + d], s16[u], acc));
    }
    g_A[k * 16 + n] = acc * 0.0625f;

    if (blockIdx.x == 0) {
        if (tid < 16) {
            float cc = 0.f;
#pragma unroll
            for (int d = 0; d < 16; d++) {
                int u = (tid * d) & 15;
                cc += (br[d] - bi[d]) * c16[u] - (br[d] + bi[d]) * s16[u];
            }
            g_c[tid] = cc * 0.0625f;
            float scale = gamma[tid] * rsqrtf(mvar[tid] + 1e-5f);
            g_kb[tid] = (dwb[tid] - mmean[tid]) * scale + beta[tid];
        }
        if (tid < 144) {
            int d = tid & 15;
            float scale = gamma[d] * rsqrtf(mvar[d] + 1e-5f);
            g_kw[tid] = dwk[tid] * scale;
        }
    }
}

// ---------------------------------------------------------------------------
// main GEMM: y[patch, n] = A[n,:] . p + c[n]
// block = 128 threads = one (b, ph) patch row (256 patches)
// thread: cg = t&3 (4 channels), pg = t>>2; owns patches p = jj*32+pg, jj=0..7
// cp.async double-buffered row pipeline; XOR-swizzled smem layout:
//   16B chunk for (patch p, chunk c) stored at chunk index p*4 + (c ^ ((p>>1)&3))
// Conflict-free for both the LDGSTS write pattern and the LDS.128 read pattern.
// ---------------------------------------------------------------------------
__global__ void __launch_bounds__(128) fno_gemm_kernel(const float* __restrict__ x)
{
    __shared__ float xs[2][4096];        // two 16KB row buffers (swizzled)
    __shared__ float As[FIN * ND];       // A: [k][16]

    int t   = threadIdx.x;
    int bid = blockIdx.x;                // b*256 + ph
    int b   = bid >> 8;
    int ph  = bid & 255;

    const float* xbase = x + (size_t)(b * 4096 + ph * 16) * 4096;

    // per-thread swizzled destination byte offsets for the 8 chunks it copies
    uint32_t xs0 = smem_u32(&xs[0][0]);
    uint32_t xs1 = smem_u32(&xs[1][0]);
    uint32_t dstoff[8];
#pragma unroll
    for (int it = 0; it < 8; it++) {
        int g4 = t + it * 128;           // global 16B-chunk index 0..1023
        int p  = g4 >> 2, c = g4 & 3;
        int cc = c ^ ((p >> 1) & 3);
        dstoff[it] = (uint32_t)((p * 4 + cc) << 4);
    }

    // kick off row 0 before anything else
    {
        const char* src = (const char*)xbase;
#pragma unroll
        for (int it = 0; it < 8; it++)
            cp_async16(xs0 + dstoff[it], src + ((t + it * 128) << 4));
        asm volatile("cp.async.commit_group;");
    }

    {   // stage A into smem (4096 floats) — overlaps with row-0 cp.async
        const float4* A4  = (const float4*)g_A;
        float4*       As4 = (float4*)As;
#pragma unroll
        for (int it = 0; it < 8; it++)
            As4[t + it * 128] = A4[t + it * 128];
    }

    int cg  = t & 3;
    int pg  = t >> 2;                    // 0..31
    int swz = (pg >> 1) & 3;             // read-side swizzle key (p>>1)&3 == (pg>>1)&3
    float4 acc[8];
#pragma unroll
    for (int jj = 0; jj < 8; jj++) acc[jj] = make_float4(0.f, 0.f, 0.f, 0.f);

    for (int kr = 0; kr < 16; kr++) {
        // issue next row into the other buffer (it was fully consumed at kr-1)
        if (kr < 15) {
            uint32_t dbuf = ((kr + 1) & 1) ? xs1 : xs0;
            const char* src = (const char*)(xbase + (size_t)(kr + 1) * 4096);
#pragma unroll
            for (int it = 0; it < 8; it++)
                cp_async16(dbuf + dstoff[it], src + ((t + it * 128) << 4));
            asm volatile("cp.async.commit_group;");
            asm volatile("cp.async.wait_group 1;");   // row kr complete
        } else {
            asm volatile("cp.async.wait_group 0;");   // last row
        }
        __syncthreads();                 // all threads' chunks visible (+ As on kr=0)

        const float* xb = xs[kr & 1];
#pragma unroll
        for (int kc4 = 0; kc4 < 4; kc4++) {
            int k0 = kr * 16 + kc4 * 4;
            const float* Ab = &As[k0 * 16 + cg * 4];
            float4 A0 = *(const float4*)(Ab);
            float4 A1 = *(const float4*)(Ab + 16);
            float4 A2 = *(const float4*)(Ab + 32);
            float4 A3 = *(const float4*)(Ab + 48);
            int co = (kc4 ^ swz) << 2;   // swizzled float offset within patch
#pragma unroll
            for (int jj = 0; jj < 8; jj++) {
                int p = jj * 32 + pg;
                float4 xv = *(const float4*)&xb[p * 16 + co];
                acc[jj].x = fmaf(xv.x, A0.x, fmaf(xv.y, A1.x, fmaf(xv.z, A2.x, fmaf(xv.w, A3.x, acc[jj].x))));
                acc[jj].y = fmaf(xv.x, A0.y, fmaf(xv.y, A1.y, fmaf(xv.z, A2.y, fmaf(xv.w, A3.y, acc[jj].y))));
                acc[jj].z = fmaf(xv.x, A0.z, fmaf(xv.y, A1.z, fmaf(xv.z, A2.z, fmaf(xv.w, A3.z, acc[jj].z))));
                acc[jj].w = fmaf(xv.x, A0.w, fmaf(xv.y, A1.w, fmaf(xv.z, A2.w, fmaf(xv.w, A3.w, acc[jj].w))));
            }
        }
        __syncthreads();                 // buffer (kr&1) free for reuse at kr+1's issue
    }

    float4 cc = ((const float4*)g_c)[cg];
    float4* y4 = (float4*)g_y;
#pragma unroll
    for (int jj = 0; jj < 8; jj++) {
        int p = jj * 32 + pg;
        float4 o = acc[jj];
        o.x += cc.x; o.y += cc.y; o.z += cc.z; o.w += cc.w;
        y4[(bid * 256 + p) * 4 + cg] = o;
    }
}

// ---------------------------------------------------------------------------
// depthwise 3x3 SAME conv (BN folded) at resized positions.
// Two vertical outputs per thread: i = 2*iq and 2*iq+1 share row 4*iq+2.
// ---------------------------------------------------------------------------
__global__ void __launch_bounds__(256) conv_resize_kernel(float* __restrict__ out)
{
    int lin = blockIdx.x * 256 + threadIdx.x;   // 0..65535
    int cg = lin & 3;
    int j  = (lin >> 2) & 127;
    int iq = (lin >> 9) & 63;
    int b  = lin >> 15;

    int i0 = 2 * iq;
    int c1 = 2 * j + 1;
    int rbase = 4 * iq;                          // = (2*i0+1) - 1

    const float4* y4  = (const float4*)g_y;
    const float4* kw4 = (const float4*)g_kw;
    float4 kb = ((const float4*)g_kb)[cg];
    float4 s0 = kb, s1 = kb;

#pragma unroll
    for (int rr = 0; rr < 5; rr++) {
        int r = rbase + rr;
        if (r > 255) continue;                   // only rr=4 at iq=63
#pragma unroll
        for (int dx = -1; dx <= 1; dx++) {
            int c = c1 + dx;                     // c >= 0 always
            if (c > 255) continue;
            float4 v = y4[((b * 256 + r) * 256 + c) * 4 + cg];
            if (rr < 3) {                        // output i0: taps rows rr=0,1,2
                float4 w = kw4[(rr * 3 + (dx + 1)) * 4 + cg];
                s0.x = fmaf(v.x, w.x, s0.x);
                s0.y = fmaf(v.y, w.y, s0.y);
                s0.z = fmaf(v.z, w.z, s0.z);
                s0.w = fmaf(v.w, w.w, s0.w);
            }
            if (rr >= 2) {                       // output i0+1: taps rows rr=2,3,4
                float4 w = kw4[((rr - 2) * 3 + (dx + 1)) * 4 + cg];
                s1.x = fmaf(v.x, w.x, s1.x);
                s1.y = fmaf(v.y, w.y, s1.y);
                s1.z = fmaf(v.z, w.z, s1.z);
                s1.w = fmaf(v.w, w.w, s1.w);
            }
        }
    }
    float4* o4 = (float4*)out;
    o4[((b * 128 + i0) * 128 + j) * 4 + cg]       = s0;
    o4[((b * 128 + i0 + 1) * 128 + j) * 4 + cg]   = s1;
}

// ---------------------------------------------------------------------------
extern "C" void kernel_launch(void* const* d_in, const int* in_sizes, int n_in,
                              void* d_out, int out_size)
{
    const float* x     = (const float*)d_in[0];
    const float* Wr    = (const float*)d_in[1];
    const float* br    = (const float*)d_in[2];
    const float* Wi    = (const float*)d_in[3];
    const float* bi    = (const float*)d_in[4];
    const float* dwk   = (const float*)d_in[5];
    const float* dwb   = (const float*)d_in[6];
    const float* gamma = (const float*)d_in[7];
    const float* beta  = (const float*)d_in[8];
    const float* mmean = (const float*)d_in[9];
    const float* mvar  = (const float*)d_in[10];

    pre1_kernel<<<16, 256>>>(Wr, Wi);
    pre2_kernel<<<16, 256>>>(br, bi, dwk, dwb, gamma, beta, mmean, mvar);
    fno_gemm_kernel<<<512, 128>>>(x);
    conv_resize_kernel<<<256, 256>>>((float*)d_out);
}

// round 4
// speedup vs baseline: 1.1384x; 1.0500x over previous
#include <cuda_runtime.h>
#include <math.h>
#include <stdint.h>

#define FIN 256
#define ND  16

// scratch (static device arrays — no allocations)
__device__ float g_Gr[FIN*ND];
__device__ float g_Gi[FIN*ND];
__device__ float g_A [FIN*ND];          // [k][n]
__device__ float g_c [ND];
__device__ float g_kw[9*ND];            // BN-folded depthwise weights [tap][d]
__device__ float g_kb[ND];              // BN-folded bias
__device__ float g_y [2*256*256*ND];    // intermediate y grid (8 MB)

__device__ __forceinline__ uint32_t smem_u32(const void* p) {
    uint32_t a;
    asm("{ .reg .u64 t; cvta.to.shared.u64 t, %1; cvt.u32.u64 %0, t; }"
        : "=r"(a) : "l"(p));
    return a;
}
__device__ __forceinline__ void cp_async16(uint32_t dst, const void* src) {
    asm volatile("cp.async.cg.shared.global [%0], [%1], 16;" :: "r"(dst), "l"(src));
}

// ---------------------------------------------------------------------------
// pre1: G[k,d] = sum_m e^{-2pi i m k/256} (Wr[m,d] + i Wi[m,d])
// ---------------------------------------------------------------------------
__global__ void __launch_bounds__(256) pre1_kernel(const float* __restrict__ Wr,
                                                   const float* __restrict__ Wi)
{
    __shared__ float ct[256], st[256];
    int tid = threadIdx.x;
    {
        float ang = 6.283185307179586f * (float)tid / 256.0f;
        float s, c; sincosf(ang, &s, &c);
        ct[tid] = c; st[tid] = s;
    }
    __syncthreads();

    int i = blockIdx.x * 256 + tid;      // 0..4095
    int k = i >> 4, d = i & 15;
    float grA = 0.f, giA = 0.f, grB = 0.f, giB = 0.f;
#pragma unroll 4
    for (int m = 0; m < 256; m += 2) {
        int t0 = (m * k) & 255;
        int t1 = ((m + 1) * k) & 255;
        float c0 = ct[t0], s0 = st[t0];
        float c1 = ct[t1], s1 = st[t1];
        float wr0 = Wr[m * 16 + d],       wi0 = Wi[m * 16 + d];
        float wr1 = Wr[(m + 1) * 16 + d], wi1 = Wi[(m + 1) * 16 + d];
        grA = fmaf(c0, wr0, fmaf(s0, wi0, grA));
        giA = fmaf(c0, wi0, fmaf(-s0, wr0, giA));
        grB = fmaf(c1, wr1, fmaf(s1, wi1, grB));
        giB = fmaf(c1, wi1, fmaf(-s1, wr1, giB));
    }
    g_Gr[i] = grA + grB;
    g_Gi[i] = giA + giB;
}

// ---------------------------------------------------------------------------
// pre2: A[k,n] = (1/16) sum_d [Gr cos(2pi nd/16) - Gi sin(2pi nd/16)]
//       c[n], BN-folded conv weights/bias
// ---------------------------------------------------------------------------
__global__ void __launch_bounds__(256) pre2_kernel(const float* __restrict__ br,
                                                   const float* __restrict__ bi,
                                                   const float* __restrict__ dwk,
                                                   const float* __restrict__ dwb,
                                                   const float* __restrict__ gamma,
                                                   const float* __restrict__ beta,
                                                   const float* __restrict__ mmean,
                                                   const float* __restrict__ mvar)
{
    __shared__ float c16[16], s16[16];
    int tid = threadIdx.x;
    if (tid < 16) {
        float ang = 6.283185307179586f * (float)tid / 16.0f;
        float s, c; sincosf(ang, &s, &c);
        c16[tid] = c; s16[tid] = s;
    }
    __syncthreads();

    int i = blockIdx.x * 256 + tid;      // 0..4095
    int k = i >> 4, n = i & 15;
    float acc = 0.f;
#pragma unroll
    for (int d = 0; d < 16; d++) {
        int u = (n * d) & 15;
        acc = fmaf(g_Gr[k * 16 + d], c16[u], fmaf(-g_Gi[k * 16 + d], s16[u], acc));
    }
    g_A[k * 16 + n] = acc * 0.0625f;

    if (blockIdx.x == 0) {
        if (tid < 16) {
            float cc = 0.f;
#pragma unroll
            for (int d = 0; d < 16; d++) {
                int u = (tid * d) & 15;
                cc += (br[d] - bi[d]) * c16[u] - (br[d] + bi[d]) * s16[u];
            }
            g_c[tid] = cc * 0.0625f;
            float scale = gamma[tid] * rsqrtf(mvar[tid] + 1e-5f);
            g_kb[tid] = (dwb[tid] - mmean[tid]) * scale + beta[tid];
        }
        if (tid < 144) {
            int d = tid & 15;
            float scale = gamma[d] * rsqrtf(mvar[d] + 1e-5f);
            g_kw[tid] = dwk[tid] * scale;
        }
    }
}

// ---------------------------------------------------------------------------
// main GEMM: y[patch, n] = A[n,:] . p + c[n]
// block = 128 threads = 4 warps; warp w owns 64 contiguous patches.
// Each warp has a PRIVATE 2x4KB cp.async double-buffer -> no __syncthreads in
// the mainloop; per-row sync is wait_group + __syncwarp only.
// lane: cg = lane&3 (4 n-values), pg = lane>>2; patches p_local = jj*8+pg.
// XOR swizzle: chunk(p,c) stored at p*4 + (c ^ ((p>>1)&3)); read key (pg>>1)&3.
// ---------------------------------------------------------------------------
__global__ void __launch_bounds__(128, 4) fno_gemm_kernel(const float* __restrict__ x)
{
    __shared__ float xs[4][2][1024];     // [warp][buf][64 patches * 16 floats]
    __shared__ float As[FIN * ND];       // A: [k][16]

    int t    = threadIdx.x;
    int w    = t >> 5;
    int lane = t & 31;
    int bid  = blockIdx.x;               // b*256 + ph
    int b    = bid >> 8;
    int ph   = bid & 255;

    // this warp's slice of the image row: 64 patches * 16 floats = 1024 floats
    const float* xbase = x + (size_t)(b * 4096 + ph * 16) * 4096 + w * 1024;

    uint32_t buf[2] = { smem_u32(&xs[w][0][0]), smem_u32(&xs[w][1][0]) };
    uint32_t dstoff[8];
#pragma unroll
    for (int it = 0; it < 8; it++) {
        int g4 = lane + it * 32;         // chunk index within warp slice 0..255
        int p  = g4 >> 2, c = g4 & 3;
        int cc = c ^ ((p >> 1) & 3);
        dstoff[it] = (uint32_t)((p * 4 + cc) << 4);
    }

    // kick off row 0
    {
        const char* src = (const char*)xbase;
#pragma unroll
        for (int it = 0; it < 8; it++)
            cp_async16(buf[0] + dstoff[it], src + ((lane + it * 32) << 4));
        asm volatile("cp.async.commit_group;");
    }

    {   // stage A into smem (4096 floats) — overlaps with row-0 cp.async
        const float4* A4  = (const float4*)g_A;
        float4*       As4 = (float4*)As;
#pragma unroll
        for (int it = 0; it < 8; it++)
            As4[t + it * 128] = A4[t + it * 128];
    }
    __syncthreads();                     // As visible to all warps (once, pre-loop)

    int cg  = lane & 3;
    int pg  = lane >> 2;                 // 0..7
    int swz = (pg >> 1) & 3;             // read-side swizzle key
    float4 acc[8];
#pragma unroll
    for (int jj = 0; jj < 8; jj++) acc[jj] = make_float4(0.f, 0.f, 0.f, 0.f);

    for (int kr = 0; kr < 16; kr++) {
        if (kr < 15) {
            uint32_t dbuf = buf[(kr + 1) & 1];
            const char* src = (const char*)(xbase + (size_t)(kr + 1) * 4096);
#pragma unroll
            for (int it = 0; it < 8; it++)
                cp_async16(dbuf + dstoff[it], src + ((lane + it * 32) << 4));
            asm volatile("cp.async.commit_group;");
            asm volatile("cp.async.wait_group 1;");   // row kr landed
        } else {
            asm volatile("cp.async.wait_group 0;");
        }
        __syncwarp();                    // all lanes' chunks of row kr visible

        const float* xb = xs[w][kr & 1];
#pragma unroll
        for (int kc4 = 0; kc4 < 4; kc4++) {
            int k0 = kr * 16 + kc4 * 4;
            const float* Ab = &As[k0 * 16 + cg * 4];
            float4 A0 = *(const float4*)(Ab);
            float4 A1 = *(const float4*)(Ab + 16);
            float4 A2 = *(const float4*)(Ab + 32);
            float4 A3 = *(const float4*)(Ab + 48);
            int co = (kc4 ^ swz) << 2;   // swizzled float offset within patch
#pragma unroll
            for (int jj = 0; jj < 8; jj++) {
                int p = jj * 8 + pg;     // local patch 0..63
                float4 xv = *(const float4*)&xb[p * 16 + co];
                acc[jj].x = fmaf(xv.x, A0.x, fmaf(xv.y, A1.x, fmaf(xv.z, A2.x, fmaf(xv.w, A3.x, acc[jj].x))));
                acc[jj].y = fmaf(xv.x, A0.y, fmaf(xv.y, A1.y, fmaf(xv.z, A2.y, fmaf(xv.w, A3.y, acc[jj].y))));
                acc[jj].z = fmaf(xv.x, A0.z, fmaf(xv.y, A1.z, fmaf(xv.z, A2.z, fmaf(xv.w, A3.z, acc[jj].z))));
                acc[jj].w = fmaf(xv.x, A0.w, fmaf(xv.y, A1.w, fmaf(xv.z, A2.w, fmaf(xv.w, A3.w, acc[jj].w))));
            }
        }
        __syncwarp();                    // buffer (kr&1) free before re-issue at kr+1
    }

    float4 cc = ((const float4*)g_c)[cg];
    float4* y4 = (float4*)g_y;
#pragma unroll
    for (int jj = 0; jj < 8; jj++) {
        int gp = bid * 256 + w * 64 + jj * 8 + pg;   // global patch
        float4 o = acc[jj];
        o.x += cc.x; o.y += cc.y; o.z += cc.z; o.w += cc.w;
        y4[gp * 4 + cg] = o;
    }
}

// ---------------------------------------------------------------------------
// depthwise 3x3 SAME conv (BN folded) at resized positions.
// Two vertical outputs per thread: i = 2*iq and 2*iq+1 share row 4*iq+2.
// ---------------------------------------------------------------------------
__global__ void __launch_bounds__(128) conv_resize_kernel(float* __restrict__ out)
{
    int lin = blockIdx.x * 128 + threadIdx.x;   // 0..65535
    int cg = lin & 3;
    int j  = (lin >> 2) & 127;
    int iq = (lin >> 9) & 63;
    int b  = lin >> 15;

    int i0 = 2 * iq;
    int c1 = 2 * j + 1;
    int rbase = 4 * iq;                          // = (2*i0+1) - 1

    const float4* y4  = (const float4*)g_y;
    const float4* kw4 = (const float4*)g_kw;
    float4 kb = ((const float4*)g_kb)[cg];
    float4 s0 = kb, s1 = kb;

#pragma unroll
    for (int rr = 0; rr < 5; rr++) {
        int r = rbase + rr;
        if (r > 255) continue;                   // only rr=4 at iq=63
#pragma unroll
        for (int dx = -1; dx <= 1; dx++) {
            int c = c1 + dx;                     // c >= 0 always
            if (c > 255) continue;
            float4 v = y4[((b * 256 + r) * 256 + c) * 4 + cg];
            if (rr < 3) {                        // output i0: taps rows rr=0,1,2
                float4 w = kw4[(rr * 3 + (dx + 1)) * 4 + cg];
                s0.x = fmaf(v.x, w.x, s0.x);
                s0.y = fmaf(v.y, w.y, s0.y);
                s0.z = fmaf(v.z, w.z, s0.z);
                s0.w = fmaf(v.w, w.w, s0.w);
            }
            if (rr >= 2) {                       // output i0+1: taps rows rr=2,3,4
                float4 w = kw4[((rr - 2) * 3 + (dx + 1)) * 4 + cg];
                s1.x = fmaf(v.x, w.x, s1.x);
                s1.y = fmaf(v.y, w.y, s1.y);
                s1.z = fmaf(v.z, w.z, s1.z);
                s1.w = fmaf(v.w, w.w, s1.w);
            }
        }
    }
    float4* o4 = (float4*)out;
    o4[((b * 128 + i0) * 128 + j) * 4 + cg]       = s0;
    o4[((b * 128 + i0 + 1) * 128 + j) * 4 + cg]   = s1;
}

// ---------------------------------------------------------------------------
extern "C" void kernel_launch(void* const* d_in, const int* in_sizes, int n_in,
                              void* d_out, int out_size)
{
    const float* x     = (const float*)d_in[0];
    const float* Wr    = (const float*)d_in[1];
    const float* br    = (const float*)d_in[2];
    const float* Wi    = (const float*)d_in[3];
    const float* bi    = (const float*)d_in[4];
    const float* dwk   = (const float*)d_in[5];
    const float* dwb   = (const float*)d_in[6];
    const float* gamma = (const float*)d_in[7];
    const float* beta  = (const float*)d_in[8];
    const float* mmean = (const float*)d_in[9];
    const float* mvar  = (const float*)d_in[10];

    pre1_kernel<<<16, 256>>>(Wr, Wi);
    pre2_kernel<<<16, 256>>>(br, bi, dwk, dwb, gamma, beta, mmean, mvar);
    fno_gemm_kernel<<<512, 128>>>(x);
    conv_resize_kernel<<<512, 128>>>((float*)d_out);
}